// round 1
// baseline (speedup 1.0000x reference)
#include <cuda_runtime.h>
#include <cstdint>

// ---------------- problem constants ----------------
// F_T=4, H_T=32, W_T=32 -> T=4096, K=3, P=1
// HEADS=8, DIM_HEAD=64, DIM=512, INNER=512, batch=2
// tokens used: 0..4095 per batch (pad token provably unused in output)
#define NTOK      4096
#define BATCH     2
#define MROWS     (BATCH * NTOK)        // 8192
#define DIM       512
#define INNER     512
#define KVN       1024
#define NPOS      4095                   // attention positions actually needed (i = 0..4094)
#define SCALE_Q   0.125f                 // 64^-0.5

// ---------------- scratch (no allocations allowed) ----------------
__device__ float g_q [MROWS * INNER];    // 16.8 MB  : x @ Wq      (tokens 0..4095)
__device__ float g_kv[MROWS * KVN];      // 33.6 MB  : x @ Wkv     ([k | v] per row)
__device__ float g_z [MROWS * INNER];    // 16.8 MB  : attention output rows (heads concat)

// ---------------- generic 128x128x8 SGEMM, 256 thr, 8x8/thread ----------------
template<int BIAS>
__global__ __launch_bounds__(256)
void sgemm128(const float* __restrict__ A, const float* __restrict__ B,
              const float* __restrict__ bias, float* __restrict__ C,
              int N, int K)
{
    __shared__ float As[8][128];
    __shared__ float Bs[8][128];

    const int tid  = threadIdx.x;
    const int tx   = tid & 15;
    const int ty   = tid >> 4;
    const int row0 = blockIdx.y * 128;
    const int col0 = blockIdx.x * 128;

    // A tile loader: 128 rows x 8 cols, float4 per thread
    const int ar = tid >> 1;
    const int ac = (tid & 1) * 4;
    // B tile loader: 8 rows x 128 cols, float4 per thread
    const int br = tid >> 5;
    const int bc = (tid & 31) * 4;

    const float* Ap = A + (long)(row0 + ar) * K + ac;
    const float* Bp = B + (long)br * N + col0 + bc;

    float acc[8][8];
    #pragma unroll
    for (int i = 0; i < 8; i++)
        #pragma unroll
        for (int j = 0; j < 8; j++) acc[i][j] = 0.f;

    for (int kk = 0; kk < K; kk += 8) {
        float4 av = *(const float4*)(Ap + kk);
        float4 bv = *(const float4*)(Bp + (long)kk * N);
        As[ac + 0][ar] = av.x;
        As[ac + 1][ar] = av.y;
        As[ac + 2][ar] = av.z;
        As[ac + 3][ar] = av.w;
        *(float4*)&Bs[br][bc] = bv;
        __syncthreads();

        #pragma unroll
        for (int k = 0; k < 8; k++) {
            float a[8], b[8];
            #pragma unroll
            for (int i = 0; i < 8; i++) a[i] = As[k][ty * 8 + i];
            #pragma unroll
            for (int j = 0; j < 8; j++) b[j] = Bs[k][tx * 8 + j];
            #pragma unroll
            for (int i = 0; i < 8; i++)
                #pragma unroll
                for (int j = 0; j < 8; j++)
                    acc[i][j] += a[i] * b[j];
        }
        __syncthreads();
    }

    #pragma unroll
    for (int i = 0; i < 8; i++) {
        const long r = row0 + ty * 8 + i;
        #pragma unroll
        for (int j = 0; j < 8; j += 4) {
            const int c = col0 + tx * 8 + j;
            float4 o;
            o.x = acc[i][j + 0];
            o.y = acc[i][j + 1];
            o.z = acc[i][j + 2];
            o.w = acc[i][j + 3];
            if (BIAS) {
                o.x += bias[c + 0];
                o.y += bias[c + 1];
                o.z += bias[c + 2];
                o.w += bias[c + 3];
            }
            *(float4*)(C + r * N + c) = o;
        }
    }
}

// ---------------- BOS row: z[b,0,:] = v(token 0) ----------------
__global__ void bos_copy_kernel()
{
    const int b = blockIdx.x;      // 0..1
    const int t = threadIdx.x;     // 0..511
    g_z[(long)b * NTOK * INNER + t] = g_kv[(long)b * NTOK * KVN + 512 + t];
}

// ---------------- windowed attention: one warp per (b,h,i) ----------------
__global__ __launch_bounds__(256)
void attn_kernel()
{
    const int widx = blockIdx.x * 8 + (threadIdx.x >> 5);
    const int lane = threadIdx.x & 31;
    if (widx >= 16 * NPOS) return;

    const int i  = widx % NPOS;          // position 0..4094
    const int bh = widx / NPOS;          // 0..15
    const int h  = bh & 7;
    const int b  = bh >> 3;
    const long bbase = (long)b * NTOK;

    // decode (f, hh, w)
    const int f  = i >> 10;
    const int hh = (i >> 5) & 31;
    const int w  = i & 31;

    // per-lane slot: lane 0 = BOS (token 0); lanes 1..27 = window offsets
    int tok = 0;
    int valid = 0;
    if (lane == 0) {
        valid = 1;              // BOS, token 0
    } else if (lane <= 27) {
        const int t  = lane - 1;
        const int df = t / 9 - 1;
        const int dh = (t / 3) % 3 - 1;
        const int dw = t % 3 - 1;
        const int nf = f + df, nh = hh + dh, nw = w + dw;
        if ((unsigned)nf < 4u && (unsigned)nh < 32u && (unsigned)nw < 32u) {
            const int j = (nf << 10) | (nh << 5) | nw;
            if (j <= i) { valid = 1; tok = j + 1; }   // token = position + 1
        }
    }

    // q for position i = token i+1, scaled
    float2 qv = *(const float2*)(g_q + (bbase + i + 1) * INNER + h * 64 + 2 * lane);
    qv.x *= SCALE_Q;
    qv.y *= SCALE_Q;

    const float NEG_INF = __int_as_float(0xff800000);
    float my_sim = NEG_INF;

    // sims: loop slots, coalesced k load, butterfly reduce
    for (int s = 0; s < 28; s++) {
        const int vs = __shfl_sync(0xffffffffu, valid, s);
        const int ts = __shfl_sync(0xffffffffu, tok, s);
        if (vs) {
            float2 kk = *(const float2*)(g_kv + (bbase + ts) * KVN + h * 64 + 2 * lane);
            float part = qv.x * kk.x + qv.y * kk.y;
            #pragma unroll
            for (int off = 16; off; off >>= 1)
                part += __shfl_xor_sync(0xffffffffu, part, off);
            if (lane == s) my_sim = part;
        }
    }

    // warp softmax over the 28 slots (invalid lanes hold -inf -> weight 0)
    float m = my_sim;
    #pragma unroll
    for (int off = 16; off; off >>= 1)
        m = fmaxf(m, __shfl_xor_sync(0xffffffffu, m, off));
    const float p = __expf(my_sim - m);
    float denom = p;
    #pragma unroll
    for (int off = 16; off; off >>= 1)
        denom += __shfl_xor_sync(0xffffffffu, denom, off);
    const float inv = 1.f / denom;

    // PV: broadcast weight per slot, coalesced v load
    float2 acc = make_float2(0.f, 0.f);
    for (int s = 0; s < 28; s++) {
        const int   vs = __shfl_sync(0xffffffffu, valid, s);
        const int   ts = __shfl_sync(0xffffffffu, tok, s);
        const float ps = __shfl_sync(0xffffffffu, p, s);
        if (vs) {
            float2 vv = *(const float2*)(g_kv + (bbase + ts) * KVN + 512 + h * 64 + 2 * lane);
            acc.x += ps * vv.x;
            acc.y += ps * vv.y;
        }
    }

    float* zp = g_z + (bbase + i + 1) * INNER + h * 64 + 2 * lane;
    *(float2*)zp = make_float2(acc.x * inv, acc.y * inv);
}

// ---------------- launch ----------------
extern "C" void kernel_launch(void* const* d_in, const int* in_sizes, int n_in,
                              void* d_out, int out_size)
{
    const float* x   = (const float*)d_in[0];   // (2,4096,512)
    const float* Wq  = (const float*)d_in[1];   // (512,512)
    const float* Wkv = (const float*)d_in[2];   // (512,1024)
    const float* Wo  = (const float*)d_in[3];   // (512,512)
    const float* bo  = (const float*)d_in[4];   // (512,)
    float* out = (float*)d_out;                 // (2,4096,512)

    float *qp, *kvp, *zp;
    cudaGetSymbolAddress((void**)&qp,  g_q);
    cudaGetSymbolAddress((void**)&kvp, g_kv);
    cudaGetSymbolAddress((void**)&zp,  g_z);

    // 1) projections (x is contiguous 8192x512; pad token never needed)
    sgemm128<0><<<dim3(INNER / 128, MROWS / 128), 256>>>(x, Wq,  nullptr, qp,  INNER, DIM);
    sgemm128<0><<<dim3(KVN   / 128, MROWS / 128), 256>>>(x, Wkv, nullptr, kvp, KVN,   DIM);

    // 2) BOS passthrough rows
    bos_copy_kernel<<<BATCH, 512>>>();

    // 3) windowed causal attention -> g_z rows 1..4095 per batch
    attn_kernel<<<(16 * NPOS + 7) / 8, 256>>>();

    // 4) output projection + bias
    sgemm128<1><<<dim3(DIM / 128, MROWS / 128), 256>>>(zp, Wo, bo, out, DIM, DIM);
}

// round 3
// speedup vs baseline: 1.9548x; 1.9548x over previous
#include <cuda_runtime.h>
#include <cstdint>

// ---------------- problem constants ----------------
#define NTOK      4096
#define BATCH     2
#define MROWS     (BATCH * NTOK)        // 8192
#define DIM       512
#define INNER     512
#define KVN       1024
#define NPOS      4095
#define SCALE_Q   0.125f

// ---------------- scratch ----------------
__device__ float g_q [MROWS * INNER];
__device__ float g_kv[MROWS * KVN];
__device__ float g_z [MROWS * INNER];

// ---------------- tf32 helpers ----------------
__device__ __forceinline__ uint32_t f2tf32(float x) {
    uint32_t u;
    asm("cvt.rna.tf32.f32 %0, %1;" : "=r"(u) : "f"(x));
    return u;
}

__device__ __forceinline__ void mma_tf32(float& d0, float& d1, float& d2, float& d3,
                                         uint32_t a0, uint32_t a1, uint32_t a2, uint32_t a3,
                                         uint32_t b0, uint32_t b1) {
    asm volatile(
        "mma.sync.aligned.m16n8k8.row.col.f32.tf32.tf32.f32 "
        "{%0,%1,%2,%3}, {%4,%5,%6,%7}, {%8,%9}, {%0,%1,%2,%3};"
        : "+f"(d0), "+f"(d1), "+f"(d2), "+f"(d3)
        : "r"(a0), "r"(a1), "r"(a2), "r"(a3), "r"(b0), "r"(b1));
}

// ---------------- tf32 tensor-core GEMM: 128x128x16 tiles, 256 thr ----------------
// A: MxK row-major fp32, B: KxN row-major fp32, C: MxN fp32 (+optional bias)
#define TG_STRIDE 136   // smem row stride (uint32): conflict-free frag reads, 16B-aligned

template<int BIAS>
__global__ __launch_bounds__(256)
void tgemm(const float* __restrict__ A, const float* __restrict__ B,
           const float* __restrict__ bias, float* __restrict__ C,
           int N, int K)
{
    __shared__ uint32_t sA[16][TG_STRIDE];   // [k][m] (A transposed in smem)
    __shared__ uint32_t sB[16][TG_STRIDE];   // [k][n]

    const int tid  = threadIdx.x;
    const int lane = tid & 31;
    const int wid  = tid >> 5;
    const int wm   = wid >> 2;       // 0..1 -> warp m offset = wm*64
    const int wn   = wid & 3;        // 0..3 -> warp n offset = wn*32

    const int row0 = blockIdx.y * 128;
    const int col0 = blockIdx.x * 128;

    // A loader: thread -> row 0..127, two float4 covering 8 k-cols
    const int a_row = tid >> 1;
    const int a_cb  = (tid & 1) * 8;                   // col base 0 or 8
    const float* Ap = A + (long)(row0 + a_row) * K + a_cb;

    // B loader: thread -> one k row, 8 consecutive n-cols
    const int b_k  = tid >> 4;                         // 0..15
    const int b_cb = (tid & 15) * 8;                   // 0..120
    const float* Bp = B + (long)b_k * N + col0 + b_cb;

    float acc[4][4][4];
    #pragma unroll
    for (int mt = 0; mt < 4; mt++)
        #pragma unroll
        for (int nt = 0; nt < 4; nt++)
            #pragma unroll
            for (int e = 0; e < 4; e++) acc[mt][nt][e] = 0.f;

    const int KITERS = K >> 4;   // K/16

    // prologue: stage tile 0 in registers
    float4 ra0 = *(const float4*)(Ap);
    float4 ra1 = *(const float4*)(Ap + 4);
    float4 rb0 = *(const float4*)(Bp);
    float4 rb1 = *(const float4*)(Bp + 4);

    for (int kk = 0; kk < KITERS; kk++) {
        // store staged tile (convert to tf32 bits)
        sA[a_cb + 0][a_row] = f2tf32(ra0.x);
        sA[a_cb + 1][a_row] = f2tf32(ra0.y);
        sA[a_cb + 2][a_row] = f2tf32(ra0.z);
        sA[a_cb + 3][a_row] = f2tf32(ra0.w);
        sA[a_cb + 4][a_row] = f2tf32(ra1.x);
        sA[a_cb + 5][a_row] = f2tf32(ra1.y);
        sA[a_cb + 6][a_row] = f2tf32(ra1.z);
        sA[a_cb + 7][a_row] = f2tf32(ra1.w);
        {
            uint4 u0 = make_uint4(f2tf32(rb0.x), f2tf32(rb0.y), f2tf32(rb0.z), f2tf32(rb0.w));
            uint4 u1 = make_uint4(f2tf32(rb1.x), f2tf32(rb1.y), f2tf32(rb1.z), f2tf32(rb1.w));
            *(uint4*)&sB[b_k][b_cb]     = u0;
            *(uint4*)&sB[b_k][b_cb + 4] = u1;
        }
        __syncthreads();

        // prefetch next tile into registers (latency overlapped with mma below)
        if (kk + 1 < KITERS) {
            const int ko = (kk + 1) * 16;
            ra0 = *(const float4*)(Ap + ko);
            ra1 = *(const float4*)(Ap + ko + 4);
            rb0 = *(const float4*)(Bp + (long)ko * N);
            rb1 = *(const float4*)(Bp + (long)ko * N + 4);
        }

        // compute: 2 k-steps of m16n8k8
        const int r = lane >> 2;
        const int c = lane & 3;
        #pragma unroll
        for (int ks = 0; ks < 2; ks++) {
            const int kb = ks * 8;
            uint32_t af[4][4], bf[4][2];
            #pragma unroll
            for (int mt = 0; mt < 4; mt++) {
                const int row = wm * 64 + mt * 16 + r;
                af[mt][0] = sA[kb + c    ][row];
                af[mt][1] = sA[kb + c    ][row + 8];
                af[mt][2] = sA[kb + c + 4][row];
                af[mt][3] = sA[kb + c + 4][row + 8];
            }
            #pragma unroll
            for (int nt = 0; nt < 4; nt++) {
                const int cn = wn * 32 + nt * 8 + r;
                bf[nt][0] = sB[kb + c    ][cn];
                bf[nt][1] = sB[kb + c + 4][cn];
            }
            #pragma unroll
            for (int mt = 0; mt < 4; mt++)
                #pragma unroll
                for (int nt = 0; nt < 4; nt++)
                    mma_tf32(acc[mt][nt][0], acc[mt][nt][1], acc[mt][nt][2], acc[mt][nt][3],
                             af[mt][0], af[mt][1], af[mt][2], af[mt][3],
                             bf[nt][0], bf[nt][1]);
        }
        __syncthreads();
    }

    // epilogue
    const int r  = lane >> 2;
    const int cp = (lane & 3) * 2;
    #pragma unroll
    for (int mt = 0; mt < 4; mt++) {
        #pragma unroll
        for (int nt = 0; nt < 4; nt++) {
            const int cc = col0 + wn * 32 + nt * 8 + cp;
            float bx = 0.f, by = 0.f;
            if (BIAS) { bx = bias[cc]; by = bias[cc + 1]; }
            const long r1 = row0 + wm * 64 + mt * 16 + r;
            float2 o01 = make_float2(acc[mt][nt][0] + bx, acc[mt][nt][1] + by);
            float2 o23 = make_float2(acc[mt][nt][2] + bx, acc[mt][nt][3] + by);
            *(float2*)(C + r1 * N + cc)       = o01;
            *(float2*)(C + (r1 + 8) * N + cc) = o23;
        }
    }
}

// ---------------- BOS row ----------------
__global__ void bos_copy_kernel()
{
    const int b = blockIdx.x;
    const int t = threadIdx.x;
    g_z[(long)b * NTOK * INNER + t] = g_kv[(long)b * NTOK * KVN + 512 + t];
}

// ---------------- windowed attention: one warp per (b,h,i) ----------------
__global__ __launch_bounds__(256)
void attn_kernel()
{
    const int widx = blockIdx.x * 8 + (threadIdx.x >> 5);
    const int lane = threadIdx.x & 31;
    if (widx >= 16 * NPOS) return;

    const int i  = widx % NPOS;
    const int bh = widx / NPOS;
    const int h  = bh & 7;
    const int b  = bh >> 3;
    const long bbase = (long)b * NTOK;

    const int f  = i >> 10;
    const int hh = (i >> 5) & 31;
    const int w  = i & 31;

    int tok = 0;
    int valid = 0;
    if (lane == 0) {
        valid = 1;
    } else if (lane <= 27) {
        const int t  = lane - 1;
        const int df = t / 9 - 1;
        const int dh = (t / 3) % 3 - 1;
        const int dw = t % 3 - 1;
        const int nf = f + df, nh = hh + dh, nw = w + dw;
        if ((unsigned)nf < 4u && (unsigned)nh < 32u && (unsigned)nw < 32u) {
            const int j = (nf << 10) | (nh << 5) | nw;
            if (j <= i) { valid = 1; tok = j + 1; }
        }
    }

    float2 qv = *(const float2*)(g_q + (bbase + i + 1) * INNER + h * 64 + 2 * lane);
    qv.x *= SCALE_Q;
    qv.y *= SCALE_Q;

    const float NEG_INF = __int_as_float(0xff800000);
    float my_sim = NEG_INF;

    for (int s = 0; s < 28; s++) {
        const int vs = __shfl_sync(0xffffffffu, valid, s);
        const int ts = __shfl_sync(0xffffffffu, tok, s);
        if (vs) {
            float2 kk = *(const float2*)(g_kv + (bbase + ts) * KVN + h * 64 + 2 * lane);
            float part = qv.x * kk.x + qv.y * kk.y;
            #pragma unroll
            for (int off = 16; off; off >>= 1)
                part += __shfl_xor_sync(0xffffffffu, part, off);
            if (lane == s) my_sim = part;
        }
    }

    float m = my_sim;
    #pragma unroll
    for (int off = 16; off; off >>= 1)
        m = fmaxf(m, __shfl_xor_sync(0xffffffffu, m, off));
    const float p = __expf(my_sim - m);
    float denom = p;
    #pragma unroll
    for (int off = 16; off; off >>= 1)
        denom += __shfl_xor_sync(0xffffffffu, denom, off);
    const float inv = 1.f / denom;

    float2 acc = make_float2(0.f, 0.f);
    for (int s = 0; s < 28; s++) {
        const int   vs = __shfl_sync(0xffffffffu, valid, s);
        const int   ts = __shfl_sync(0xffffffffu, tok, s);
        const float ps = __shfl_sync(0xffffffffu, p, s);
        if (vs) {
            float2 vv = *(const float2*)(g_kv + (bbase + ts) * KVN + 512 + h * 64 + 2 * lane);
            acc.x += ps * vv.x;
            acc.y += ps * vv.y;
        }
    }

    float* zp = g_z + (bbase + i + 1) * INNER + h * 64 + 2 * lane;
    *(float2*)zp = make_float2(acc.x * inv, acc.y * inv);
}

// ---------------- launch ----------------
extern "C" void kernel_launch(void* const* d_in, const int* in_sizes, int n_in,
                              void* d_out, int out_size)
{
    const float* x   = (const float*)d_in[0];
    const float* Wq  = (const float*)d_in[1];
    const float* Wkv = (const float*)d_in[2];
    const float* Wo  = (const float*)d_in[3];
    const float* bo  = (const float*)d_in[4];
    float* out = (float*)d_out;

    float *qp, *kvp, *zp;
    cudaGetSymbolAddress((void**)&qp,  g_q);
    cudaGetSymbolAddress((void**)&kvp, g_kv);
    cudaGetSymbolAddress((void**)&zp,  g_z);

    tgemm<0><<<dim3(INNER / 128, MROWS / 128), 256>>>(x, Wq,  nullptr, qp,  INNER, DIM);
    tgemm<0><<<dim3(KVN   / 128, MROWS / 128), 256>>>(x, Wkv, nullptr, kvp, KVN,   DIM);

    bos_copy_kernel<<<BATCH, 512>>>();

    attn_kernel<<<(16 * NPOS + 7) / 8, 256>>>();

    tgemm<1><<<dim3(DIM / 128, MROWS / 128), 256>>>(zp, Wo, bo, out, DIM, DIM);
}

// round 6
// speedup vs baseline: 2.0030x; 1.0246x over previous
#include <cuda_runtime.h>
#include <cstdint>

// ---------------- problem constants ----------------
#define NTOK      4096
#define BATCH     2
#define MROWS     8192
#define NPOS      4095
#define SCALE_Q   0.125f
#define QKVN      1536         // fused [q | k | v] row width

// ---------------- scratch ----------------
__device__ float g_xr  [MROWS * 512];      // x, tf32-rounded
__device__ float g_qkv [MROWS * QKVN];     // fused projections
__device__ float g_z   [MROWS * 512];      // attention out (tf32-rounded)
__device__ float g_wqkvt[QKVN * 512];      // [Wq^T ; Wkv^T], tf32-rounded
__device__ float g_wot  [512 * 512];       // Wo^T, tf32-rounded

// ---------------- helpers ----------------
__device__ __forceinline__ uint32_t f2tf32(float x) {
    uint32_t u;
    asm("cvt.rna.tf32.f32 %0, %1;" : "=r"(u) : "f"(x));
    return u;
}
__device__ __forceinline__ float tf32r(float x) { return __uint_as_float(f2tf32(x)); }

__device__ __forceinline__ uint32_t smem_u32(const void* p) {
    uint32_t a;
    asm("{ .reg .u64 t; cvta.to.shared.u64 t, %1; cvt.u32.u64 %0, t; }" : "=r"(a) : "l"(p));
    return a;
}

__device__ __forceinline__ void cp16(uint32_t dst, const void* src) {
    asm volatile("cp.async.cg.shared.global [%0], [%1], 16;" :: "r"(dst), "l"(src));
}

__device__ __forceinline__ void mma_tf32(float& d0, float& d1, float& d2, float& d3,
                                         uint32_t a0, uint32_t a1, uint32_t a2, uint32_t a3,
                                         uint32_t b0, uint32_t b1) {
    asm volatile(
        "mma.sync.aligned.m16n8k8.row.col.f32.tf32.tf32.f32 "
        "{%0,%1,%2,%3}, {%4,%5,%6,%7}, {%8,%9}, {%0,%1,%2,%3};"
        : "+f"(d0), "+f"(d1), "+f"(d2), "+f"(d3)
        : "r"(a0), "r"(a1), "r"(a2), "r"(a3), "r"(b0), "r"(b1));
}

// ---------------- pre-round x to tf32 ----------------
__global__ __launch_bounds__(256)
void round_x_kernel(const float* __restrict__ in, float* __restrict__ out)
{
    const long i = ((long)blockIdx.x * 256 + threadIdx.x) * 4;
    float4 v = *(const float4*)(in + i);
    v.x = tf32r(v.x); v.y = tf32r(v.y); v.z = tf32r(v.z); v.w = tf32r(v.w);
    *(float4*)(out + i) = v;
}

// ---------------- weight transpose (+tf32 rounding) ----------------
__global__ void transpose_tf32_k(const float* __restrict__ in, float* __restrict__ out,
                                 int R, int C)   // in: R x C  ->  out: C x R
{
    __shared__ float t[32][33];
    const int bx = blockIdx.x * 32;
    const int by = blockIdx.y * 32;
    #pragma unroll
    for (int j = 0; j < 32; j += 8) {
        float v = in[(long)(by + threadIdx.y + j) * C + bx + threadIdx.x];
        t[threadIdx.y + j][threadIdx.x] = tf32r(v);
    }
    __syncthreads();
    #pragma unroll
    for (int j = 0; j < 32; j += 8)
        out[(long)(bx + threadIdx.y + j) * R + by + threadIdx.x] = t[threadIdx.x][threadIdx.y + j];
}

// ---------------- tf32 mma.sync GEMM, cp.async 4-stage, 128x128x16 ----------------
// A: M x 512 row-major fp32 (pre-rounded to tf32)
// Bt: N x 512 row-major fp32 (pre-rounded)   C: M x N
#define RSTR   20                       // smem row stride in words (conflict-free)
#define TILEW  (128 * RSTR)             // words per (A or B) tile = 2560
#define STAGEW (2 * TILEW)              // words per stage
#define NSTAGE 4
#define SMEM_WORDS (NSTAGE * STAGEW)    // 20480 words = 80KB

template<int BIAS>
__global__ __launch_bounds__(256)
void tgemm(const float* __restrict__ A, const float* __restrict__ Bt,
           const float* __restrict__ bias, float* __restrict__ C, int N)
{
    extern __shared__ uint32_t sm[];
    const uint32_t sbase = smem_u32(sm);

    const int tid  = threadIdx.x;
    const int lane = tid & 31;
    const int wid  = tid >> 5;
    const int wm   = wid >> 2;          // 0..1 -> m offset wm*64
    const int wn   = wid & 3;           // 0..3 -> n offset wn*32

    const int row0 = blockIdx.y * 128;
    const int col0 = blockIdx.x * 128;

    // loader mapping: thread -> tile row (0..127), k-half (0 or 8 floats)
    const int l_row = tid >> 1;
    const int l_kg  = (tid & 1) * 8;    // k offset in floats
    const float* Ap = A + (long)(row0 + l_row) * 512 + l_kg;
    const float* Bp = Bt + (long)(col0 + l_row) * 512 + l_kg;
    const uint32_t sA_st = (uint32_t)(l_row * RSTR + l_kg) * 4u;   // byte offset in stage
    const uint32_t sB_st = sA_st + TILEW * 4u;

    auto issue_stage = [&](int kk, int s) {
        const uint32_t so = sbase + (uint32_t)(s * STAGEW) * 4u;
        const long ko = (long)kk * 16;
        cp16(so + sA_st,      Ap + ko);
        cp16(so + sA_st + 16, Ap + ko + 4);
        cp16(so + sB_st,      Bp + ko);
        cp16(so + sB_st + 16, Bp + ko + 4);
        asm volatile("cp.async.commit_group;" ::: "memory");
    };

    float acc[4][4][4];
    #pragma unroll
    for (int mt = 0; mt < 4; mt++)
        #pragma unroll
        for (int nt = 0; nt < 4; nt++)
            #pragma unroll
            for (int e = 0; e < 4; e++) acc[mt][nt][e] = 0.f;

    // prologue: stages 0..2
    issue_stage(0, 0);
    issue_stage(1, 1);
    issue_stage(2, 2);

    const int r = lane >> 2;
    const int c = lane & 3;

    for (int kk = 0; kk < 32; kk++) {
        asm volatile("cp.async.wait_group 2;" ::: "memory");
        __syncthreads();

        if (kk + 3 < 32) issue_stage(kk + 3, (kk + 3) & 3);
        else asm volatile("cp.async.commit_group;" ::: "memory");

        const uint32_t* sa = sm + ((kk & 3) * STAGEW);
        const uint32_t* sb = sa + TILEW;

        #pragma unroll
        for (int ks = 0; ks < 2; ks++) {
            const int kb = ks * 8;
            uint32_t af[4][4], bf[4][2];
            #pragma unroll
            for (int mt = 0; mt < 4; mt++) {
                const int m = wm * 64 + mt * 16 + r;
                af[mt][0] = sa[m * RSTR + kb + c];
                af[mt][1] = sa[(m + 8) * RSTR + kb + c];
                af[mt][2] = sa[m * RSTR + kb + c + 4];
                af[mt][3] = sa[(m + 8) * RSTR + kb + c + 4];
            }
            #pragma unroll
            for (int nt = 0; nt < 4; nt++) {
                const int n = wn * 32 + nt * 8 + r;
                bf[nt][0] = sb[n * RSTR + kb + c];
                bf[nt][1] = sb[n * RSTR + kb + c + 4];
            }
            #pragma unroll
            for (int mt = 0; mt < 4; mt++)
                #pragma unroll
                for (int nt = 0; nt < 4; nt++)
                    mma_tf32(acc[mt][nt][0], acc[mt][nt][1], acc[mt][nt][2], acc[mt][nt][3],
                             af[mt][0], af[mt][1], af[mt][2], af[mt][3],
                             bf[nt][0], bf[nt][1]);
        }
        __syncthreads();
    }

    // epilogue
    const int cp = (lane & 3) * 2;
    #pragma unroll
    for (int mt = 0; mt < 4; mt++) {
        #pragma unroll
        for (int nt = 0; nt < 4; nt++) {
            const int cc = col0 + wn * 32 + nt * 8 + cp;
            float bx = 0.f, by = 0.f;
            if (BIAS) { bx = bias[cc]; by = bias[cc + 1]; }
            const long r1 = row0 + wm * 64 + mt * 16 + r;
            *(float2*)(C + r1 * N + cc)       = make_float2(acc[mt][nt][0] + bx, acc[mt][nt][1] + by);
            *(float2*)(C + (r1 + 8) * N + cc) = make_float2(acc[mt][nt][2] + bx, acc[mt][nt][3] + by);
        }
    }
}

// ---------------- BOS row: z[b,0,:] = tf32(v(token 0)) ----------------
__global__ void bos_copy_kernel()
{
    const int b = blockIdx.x;
    const int t = threadIdx.x;
    g_z[(long)b * NTOK * 512 + t] = tf32r(g_qkv[(long)b * NTOK * QKVN + 1024 + t]);
}

// ---------------- windowed attention: one warp per (b,h,i) ----------------
__global__ __launch_bounds__(256)
void attn_kernel()
{
    const int widx = blockIdx.x * 8 + (threadIdx.x >> 5);
    const int lane = threadIdx.x & 31;
    if (widx >= 16 * NPOS) return;

    const int i  = widx % NPOS;
    const int bh = widx / NPOS;
    const int h  = bh & 7;
    const int b  = bh >> 3;
    const long bbase = (long)b * NTOK;

    const int f  = i >> 10;
    const int hh = (i >> 5) & 31;
    const int w  = i & 31;

    int tok = 0;
    int valid = 0;
    if (lane == 0) {
        valid = 1;
    } else if (lane <= 27) {
        const int t  = lane - 1;
        const int df = t / 9 - 1;
        const int dh = (t / 3) % 3 - 1;
        const int dw = t % 3 - 1;
        const int nf = f + df, nh = hh + dh, nw = w + dw;
        if ((unsigned)nf < 4u && (unsigned)nh < 32u && (unsigned)nw < 32u) {
            const int j = (nf << 10) | (nh << 5) | nw;
            if (j <= i) { valid = 1; tok = j + 1; }
        }
    }

    float2 qv = *(const float2*)(g_qkv + (bbase + i + 1) * QKVN + h * 64 + 2 * lane);
    qv.x *= SCALE_Q;
    qv.y *= SCALE_Q;

    const float NEG_INF = __int_as_float(0xff800000);
    float my_sim = NEG_INF;

    for (int s = 0; s < 28; s++) {
        const int vs = __shfl_sync(0xffffffffu, valid, s);
        const int ts = __shfl_sync(0xffffffffu, tok, s);
        if (vs) {
            float2 kk = *(const float2*)(g_qkv + (bbase + ts) * QKVN + 512 + h * 64 + 2 * lane);
            float part = qv.x * kk.x + qv.y * kk.y;
            #pragma unroll
            for (int off = 16; off; off >>= 1)
                part += __shfl_xor_sync(0xffffffffu, part, off);
            if (lane == s) my_sim = part;
        }
    }

    float m = my_sim;
    #pragma unroll
    for (int off = 16; off; off >>= 1)
        m = fmaxf(m, __shfl_xor_sync(0xffffffffu, m, off));
    const float p = __expf(my_sim - m);
    float denom = p;
    #pragma unroll
    for (int off = 16; off; off >>= 1)
        denom += __shfl_xor_sync(0xffffffffu, denom, off);
    const float inv = 1.f / denom;

    float2 acc = make_float2(0.f, 0.f);
    for (int s = 0; s < 28; s++) {
        const int   vs = __shfl_sync(0xffffffffu, valid, s);
        const int   ts = __shfl_sync(0xffffffffu, tok, s);
        const float ps = __shfl_sync(0xffffffffu, p, s);
        if (vs) {
            float2 vv = *(const float2*)(g_qkv + (bbase + ts) * QKVN + 1024 + h * 64 + 2 * lane);
            acc.x += ps * vv.x;
            acc.y += ps * vv.y;
        }
    }

    float* zp = g_z + (bbase + i + 1) * 512 + h * 64 + 2 * lane;
    *(float2*)zp = make_float2(tf32r(acc.x * inv), tf32r(acc.y * inv));
}

// ---------------- launch ----------------
extern "C" void kernel_launch(void* const* d_in, const int* in_sizes, int n_in,
                              void* d_out, int out_size)
{
    const float* x   = (const float*)d_in[0];
    const float* Wq  = (const float*)d_in[1];
    const float* Wkv = (const float*)d_in[2];
    const float* Wo  = (const float*)d_in[3];
    const float* bo  = (const float*)d_in[4];
    float* out = (float*)d_out;

    float *xr, *qkv, *zp, *wqkvt, *wot;
    cudaGetSymbolAddress((void**)&xr,    g_xr);
    cudaGetSymbolAddress((void**)&qkv,   g_qkv);
    cudaGetSymbolAddress((void**)&zp,    g_z);
    cudaGetSymbolAddress((void**)&wqkvt, g_wqkvt);
    cudaGetSymbolAddress((void**)&wot,   g_wot);

    const int smbytes = SMEM_WORDS * 4;
    cudaFuncSetAttribute(tgemm<0>, cudaFuncAttributeMaxDynamicSharedMemorySize, smbytes);
    cudaFuncSetAttribute(tgemm<1>, cudaFuncAttributeMaxDynamicSharedMemorySize, smbytes);

    // 0) input rounding + weight transposes (tf32)
    round_x_kernel<<<(MROWS * 512 / 4) / 256, 256>>>(x, xr);
    transpose_tf32_k<<<dim3(16, 16), dim3(32, 8)>>>(Wq,  wqkvt,             512, 512);
    transpose_tf32_k<<<dim3(32, 16), dim3(32, 8)>>>(Wkv, wqkvt + 512 * 512, 512, 1024);
    transpose_tf32_k<<<dim3(16, 16), dim3(32, 8)>>>(Wo,  wot,               512, 512);

    // 1) fused QKV projection: 8192 x 1536 x 512
    tgemm<0><<<dim3(QKVN / 128, MROWS / 128), 256, smbytes>>>(xr, wqkvt, nullptr, qkv, QKVN);

    // 2) BOS passthrough rows
    bos_copy_kernel<<<BATCH, 512>>>();

    // 3) windowed causal attention
    attn_kernel<<<(16 * NPOS + 7) / 8, 256>>>();

    // 4) output projection + bias: 8192 x 512 x 512
    tgemm<1><<<dim3(512 / 128, MROWS / 128), 256, smbytes>>>(zp, wot, bo, out, 512);
}

// round 8
// speedup vs baseline: 2.1862x; 1.0915x over previous
#include <cuda_runtime.h>
#include <cuda_fp16.h>
#include <cstdint>

// ---------------- problem constants ----------------
#define NTOK      4096
#define BATCH     2
#define MROWS     8192
#define NPOS      4095
#define SCALE_Q   0.125f
#define QKVN      1536

// ---------------- scratch ----------------
__device__ __half g_xh   [MROWS * 512];      // x as f16
__device__ float  g_qkv  [MROWS * QKVN];     // fused projections (f32)
__device__ __half g_zh   [MROWS * 512];      // attention out (f16)
__device__ __half g_wqkvt[QKVN * 512];       // [Wq^T ; Wkv^T] f16
__device__ __half g_wot  [512 * 512];        // Wo^T f16
__device__ float  g_kt   [16 * 64 * NTOK];   // k transposed [bh][d][token]
__device__ float  g_vt   [16 * 64 * NTOK];   // v transposed

// ---------------- helpers ----------------
__device__ __forceinline__ uint32_t smem_u32(const void* p) {
    uint32_t a;
    asm("{ .reg .u64 t; cvta.to.shared.u64 t, %1; cvt.u32.u64 %0, t; }" : "=r"(a) : "l"(p));
    return a;
}
__device__ __forceinline__ void cp16(uint32_t dst, const void* src) {
    asm volatile("cp.async.cg.shared.global [%0], [%1], 16;" :: "r"(dst), "l"(src));
}
__device__ __forceinline__ void ldsm4(uint32_t& r0, uint32_t& r1, uint32_t& r2, uint32_t& r3, uint32_t a) {
    asm volatile("ldmatrix.sync.aligned.m8n8.x4.shared.b16 {%0,%1,%2,%3}, [%4];"
                 : "=r"(r0), "=r"(r1), "=r"(r2), "=r"(r3) : "r"(a));
}
__device__ __forceinline__ void ldsm2(uint32_t& r0, uint32_t& r1, uint32_t a) {
    asm volatile("ldmatrix.sync.aligned.m8n8.x2.shared.b16 {%0,%1}, [%2];"
                 : "=r"(r0), "=r"(r1) : "r"(a));
}
__device__ __forceinline__ void mma_f16(float& d0, float& d1, float& d2, float& d3,
                                        uint32_t a0, uint32_t a1, uint32_t a2, uint32_t a3,
                                        uint32_t b0, uint32_t b1) {
    asm volatile(
        "mma.sync.aligned.m16n8k16.row.col.f32.f16.f16.f32 "
        "{%0,%1,%2,%3}, {%4,%5,%6,%7}, {%8,%9}, {%0,%1,%2,%3};"
        : "+f"(d0), "+f"(d1), "+f"(d2), "+f"(d3)
        : "r"(a0), "r"(a1), "r"(a2), "r"(a3), "r"(b0), "r"(b1));
}

// ---------------- x -> f16 ----------------
__global__ __launch_bounds__(256)
void convert_x_kernel(const float* __restrict__ in, __half* __restrict__ out)
{
    const long i = ((long)blockIdx.x * 256 + threadIdx.x) * 4;
    float4 v = *(const float4*)(in + i);
    __half2 h0 = __floats2half2_rn(v.x, v.y);
    __half2 h1 = __floats2half2_rn(v.z, v.w);
    *(__half2*)(out + i)     = h0;
    *(__half2*)(out + i + 2) = h1;
}

// ---------------- weight transpose f32 -> f16^T ----------------
__global__ void transpose_h(const float* __restrict__ in, __half* __restrict__ out,
                            int R, int C)   // in: R x C -> out: C x R (f16)
{
    __shared__ float t[32][33];
    const int bx = blockIdx.x * 32;
    const int by = blockIdx.y * 32;
    #pragma unroll
    for (int j = 0; j < 32; j += 8)
        t[threadIdx.y + j][threadIdx.x] = in[(long)(by + threadIdx.y + j) * C + bx + threadIdx.x];
    __syncthreads();
    #pragma unroll
    for (int j = 0; j < 32; j += 8)
        out[(long)(bx + threadIdx.y + j) * R + by + threadIdx.x] =
            __float2half(t[threadIdx.x][threadIdx.y + j]);
}

// ---------------- f16 mma GEMM: 128x128x16, cp.async 4-stage, ldmatrix ----------------
// A: M x 512 f16 row-major; Bt: N x 512 f16 row-major; C: M x N f32 (+bias)
// smem: per stage, A tile 128 x 16 f16 @ 48B row stride (6144B), B same. 4 stages.
#define HSTAGE 12288
#define HSMEM  (4 * HSTAGE)

template<int BIAS>
__global__ __launch_bounds__(256)
void tgemm_h(const __half* __restrict__ A, const __half* __restrict__ Bt,
             const float* __restrict__ bias, float* __restrict__ C, int N)
{
    extern __shared__ char sm[];
    const uint32_t sbase = smem_u32(sm);

    const int tid  = threadIdx.x;
    const int lane = tid & 31;
    const int wid  = tid >> 5;
    const int wm   = wid >> 2;          // 0..1 -> m offset wm*64
    const int wn   = wid & 3;           // 0..3 -> n offset wn*32

    const int row0 = blockIdx.y * 128;
    const int col0 = blockIdx.x * 128;

    // loaders: thread -> (row 0..127, 16B chunk 0..1)
    const int l_row = tid >> 1;
    const int l_ch  = tid & 1;
    const __half* Ap = A  + (long)(row0 + l_row) * 512 + l_ch * 8;
    const __half* Bp = Bt + (long)(col0 + l_row) * 512 + l_ch * 8;
    const uint32_t dA = (uint32_t)(l_row * 48 + l_ch * 16);
    const uint32_t dB = dA + 6144u;

    auto issue_stage = [&](int kk, int s) {
        const uint32_t so = sbase + (uint32_t)s * HSTAGE;
        const long ko = (long)kk * 16;
        cp16(so + dA, Ap + ko);
        cp16(so + dB, Bp + ko);
        asm volatile("cp.async.commit_group;" ::: "memory");
    };

    // ldmatrix per-thread offsets
    uint32_t aoff[4], boff[4];
    {
        const int l16 = lane & 15;
        #pragma unroll
        for (int mt = 0; mt < 4; mt++)
            aoff[mt] = (uint32_t)((wm * 64 + mt * 16 + ((lane >> 3) & 1) * 8 + (lane & 7)) * 48
                                  + (lane >> 4) * 16);
        #pragma unroll
        for (int nt = 0; nt < 4; nt++)
            boff[nt] = (uint32_t)((wn * 32 + nt * 8 + (l16 & 7)) * 48 + ((l16 >> 3) & 1) * 16)
                       + 6144u;
    }

    float acc[4][4][4];
    #pragma unroll
    for (int mt = 0; mt < 4; mt++)
        #pragma unroll
        for (int nt = 0; nt < 4; nt++)
            #pragma unroll
            for (int e = 0; e < 4; e++) acc[mt][nt][e] = 0.f;

    issue_stage(0, 0);
    issue_stage(1, 1);
    issue_stage(2, 2);

    for (int kk = 0; kk < 32; kk++) {
        asm volatile("cp.async.wait_group 2;" ::: "memory");
        __syncthreads();

        if (kk + 3 < 32) issue_stage(kk + 3, (kk + 3) & 3);
        else asm volatile("cp.async.commit_group;" ::: "memory");

        const uint32_t sa = sbase + (uint32_t)(kk & 3) * HSTAGE;

        uint32_t af[4][4], bf[4][2];
        #pragma unroll
        for (int mt = 0; mt < 4; mt++)
            ldsm4(af[mt][0], af[mt][1], af[mt][2], af[mt][3], sa + aoff[mt]);
        #pragma unroll
        for (int nt = 0; nt < 4; nt++)
            ldsm2(bf[nt][0], bf[nt][1], sa + boff[nt]);

        #pragma unroll
        for (int mt = 0; mt < 4; mt++)
            #pragma unroll
            for (int nt = 0; nt < 4; nt++)
                mma_f16(acc[mt][nt][0], acc[mt][nt][1], acc[mt][nt][2], acc[mt][nt][3],
                        af[mt][0], af[mt][1], af[mt][2], af[mt][3],
                        bf[nt][0], bf[nt][1]);
    }

    // epilogue
    const int r  = lane >> 2;
    const int cp = (lane & 3) * 2;
    #pragma unroll
    for (int mt = 0; mt < 4; mt++) {
        #pragma unroll
        for (int nt = 0; nt < 4; nt++) {
            const int cc = col0 + wn * 32 + nt * 8 + cp;
            float bx = 0.f, by = 0.f;
            if (BIAS) { bx = bias[cc]; by = bias[cc + 1]; }
            const long r1 = row0 + wm * 64 + mt * 16 + r;
            *(float2*)(C + r1 * N + cc)       = make_float2(acc[mt][nt][0] + bx, acc[mt][nt][1] + by);
            *(float2*)(C + (r1 + 8) * N + cc) = make_float2(acc[mt][nt][2] + bx, acc[mt][nt][3] + by);
        }
    }
}

// ---------------- k/v transpose: g_qkv -> [bh][d][token] ----------------
__global__ void kv_transpose()
{
    __shared__ float tl[32][33];
    const int tx = threadIdx.x, ty = threadIdx.y;
    const int t0 = blockIdx.x * 32;
    const int dh = blockIdx.y;               // 0..1 (d half)
    const int z  = blockIdx.z;               // bh*2 + which
    const int which = z & 1;
    const int bh = z >> 1;
    const int b  = bh >> 3;
    const int h  = bh & 7;

    const float* src = g_qkv + 512 + which * 512 + h * 64 + dh * 32;
    #pragma unroll
    for (int j = 0; j < 32; j += 8)
        tl[ty + j][tx] = src[(long)(b * NTOK + t0 + ty + j) * QKVN + tx];
    __syncthreads();
    float* dst = (which ? g_vt : g_kt) + (long)(bh * 64 + dh * 32) * NTOK;
    #pragma unroll
    for (int j = 0; j < 32; j += 8)
        dst[(long)(ty + j) * NTOK + t0 + tx] = tl[tx][ty + j];
}

// ---------------- BOS row: zh[b,0,:] = f16(v(token 0)) ----------------
__global__ void bos_copy_kernel()
{
    const int b = blockIdx.x;
    const int t = threadIdx.x;
    g_zh[(long)b * NTOK * 512 + t] = __float2half(g_qkv[(long)b * NTOK * QKVN + 1024 + t]);
}

// ---------------- windowed attention: lane = query, no shuffles ----------------
// 15 slots: BOS + 14 causally-reachable neighbors.
__constant__ int C_DF[14] = {-1,-1,-1,-1,-1,-1,-1,-1,-1, 0, 0, 0, 0, 0};
__constant__ int C_DH[14] = {-1,-1,-1, 0, 0, 0, 1, 1, 1,-1,-1,-1, 0, 0};
__constant__ int C_DW[14] = {-1, 0, 1,-1, 0, 1,-1, 0, 1,-1, 0, 1,-1, 0};

__global__ __launch_bounds__(128, 4)
void attn_kernel()
{
    __shared__ float ssm[4][2112];

    const int w    = threadIdx.x >> 5;
    const int lane = threadIdx.x & 31;
    const int widx = blockIdx.x * 4 + w;        // 0..2047
    const int grp  = widx & 127;
    const int bh   = widx >> 7;
    const int b    = bh >> 3;
    const int h    = bh & 7;
    const int i0   = grp * 32;
    const int f    = i0 >> 10;
    const int hh   = (i0 >> 5) & 31;
    const int i    = i0 + lane;

    float* qs = ssm[w];

    // ---- stage q (coalesced), then per-lane q regs ----
    for (int r = 0; r < 32; r++) {
        const int tk = min(i0 + r, NPOS - 1) + 1;
        float2 v = *(const float2*)(g_qkv + (long)(b * NTOK + tk) * QKVN + h * 64 + 2 * lane);
        qs[r * 65 + 2 * lane]     = v.x;
        qs[r * 65 + 2 * lane + 1] = v.y;
    }
    __syncwarp();
    float q[64];
    #pragma unroll
    for (int d = 0; d < 64; d++) q[d] = qs[lane * 65 + d] * SCALE_Q;
    __syncwarp();

    // ---- per-slot sims ----
    const float NEG_INF = __int_as_float(0xff800000);
    const float* ktb = g_kt + (long)bh * 64 * NTOK;
    const float* vtb = g_vt + (long)bh * 64 * NTOK;

    float sim[15];
    int   tok[15];
    int   wok[15];

    // BOS slot
    {
        tok[0] = 0; wok[0] = 1;
        float s0 = 0.f, s1 = 0.f, s2 = 0.f, s3 = 0.f;
        #pragma unroll
        for (int d = 0; d < 64; d += 4) {
            s0 += q[d]     * ktb[(long)d * NTOK];
            s1 += q[d + 1] * ktb[(long)(d + 1) * NTOK];
            s2 += q[d + 2] * ktb[(long)(d + 2) * NTOK];
            s3 += q[d + 3] * ktb[(long)(d + 3) * NTOK];
        }
        sim[0] = (s0 + s1) + (s2 + s3);
    }

    #pragma unroll
    for (int s = 0; s < 14; s++) {
        const int df = C_DF[s], dh = C_DH[s], dw = C_DW[s];
        const int off = df * 1024 + dh * 32 + dw;
        const int warp_ok = (f + df >= 0) && ((unsigned)(hh + dh) < 32u);
        wok[s + 1] = warp_ok;
        sim[s + 1] = NEG_INF;
        int t = 0;
        if (warp_ok) {
            const int lane_ok = ((unsigned)(lane + dw) < 32u) && (i < NPOS);
            t = min(max(i + off, 0), NPOS - 1) + 1;
            float s0 = 0.f, s1 = 0.f, s2 = 0.f, s3 = 0.f;
            const float* kp = ktb + t;
            #pragma unroll
            for (int d = 0; d < 64; d += 4) {
                s0 += q[d]     * kp[(long)d * NTOK];
                s1 += q[d + 1] * kp[(long)(d + 1) * NTOK];
                s2 += q[d + 2] * kp[(long)(d + 2) * NTOK];
                s3 += q[d + 3] * kp[(long)(d + 3) * NTOK];
            }
            if (lane_ok) sim[s + 1] = (s0 + s1) + (s2 + s3);
        }
        tok[s + 1] = t;
    }

    // ---- softmax over 15 register slots ----
    float m = sim[0];
    #pragma unroll
    for (int s = 1; s < 15; s++) m = fmaxf(m, sim[s]);
    float p[15], den = 0.f;
    #pragma unroll
    for (int s = 0; s < 15; s++) { p[s] = __expf(sim[s] - m); den += p[s]; }
    const float inv = 1.f / den;
    #pragma unroll
    for (int s = 0; s < 15; s++) p[s] *= inv;

    // ---- PV: d-outer, write smem transposed ----
    float* osm = ssm[w];
    for (int d = 0; d < 64; d += 2) {
        const float* vp0 = vtb + (long)d * NTOK;
        const float* vp1 = vtb + (long)(d + 1) * NTOK;
        float a0 = 0.f, a1 = 0.f;
        #pragma unroll
        for (int s = 0; s < 15; s++) {
            if (wok[s]) {
                a0 += p[s] * vp0[tok[s]];
                a1 += p[s] * vp1[tok[s]];
            }
        }
        osm[d * 33 + lane]       = a0;
        osm[(d + 1) * 33 + lane] = a1;
    }
    __syncwarp();

    // ---- coalesced f16 store of 32 output rows ----
    for (int rr = 0; rr < 32; rr++) {
        const int irow = i0 + rr;
        if (irow < NPOS) {
            const float x0 = osm[(2 * lane) * 33 + rr];
            const float x1 = osm[(2 * lane + 1) * 33 + rr];
            *(__half2*)(g_zh + (long)(b * NTOK + irow + 1) * 512 + h * 64 + 2 * lane)
                = __floats2half2_rn(x0, x1);
        }
    }
}

// ---------------- launch ----------------
extern "C" void kernel_launch(void* const* d_in, const int* in_sizes, int n_in,
                              void* d_out, int out_size)
{
    const float* x   = (const float*)d_in[0];
    const float* Wq  = (const float*)d_in[1];
    const float* Wkv = (const float*)d_in[2];
    const float* Wo  = (const float*)d_in[3];
    const float* bo  = (const float*)d_in[4];
    float* out = (float*)d_out;

    __half *xh, *wqkvt, *wot, *zh;
    float *qkv;
    cudaGetSymbolAddress((void**)&xh,    g_xh);
    cudaGetSymbolAddress((void**)&qkv,   g_qkv);
    cudaGetSymbolAddress((void**)&zh,    g_zh);
    cudaGetSymbolAddress((void**)&wqkvt, g_wqkvt);
    cudaGetSymbolAddress((void**)&wot,   g_wot);

    cudaFuncSetAttribute(tgemm_h<0>, cudaFuncAttributeMaxDynamicSharedMemorySize, HSMEM);
    cudaFuncSetAttribute(tgemm_h<1>, cudaFuncAttributeMaxDynamicSharedMemorySize, HSMEM);

    // 0) conversions / transposes
    convert_x_kernel<<<MROWS * 512 / 4 / 256, 256>>>(x, xh);
    transpose_h<<<dim3(16, 16), dim3(32, 8)>>>(Wq,  wqkvt,             512, 512);
    transpose_h<<<dim3(32, 16), dim3(32, 8)>>>(Wkv, wqkvt + 512 * 512, 512, 1024);
    transpose_h<<<dim3(16, 16), dim3(32, 8)>>>(Wo,  wot,               512, 512);

    // 1) fused QKV projection: 8192 x 1536 x 512 (f16 mma)
    tgemm_h<0><<<dim3(QKVN / 128, MROWS / 128), 256, HSMEM>>>(xh, wqkvt, nullptr, qkv, QKVN);

    // 2) k/v transpose to [bh][d][token]
    kv_transpose<<<dim3(NTOK / 32, 2, 32), dim3(32, 8)>>>();

    // 3) BOS passthrough rows
    bos_copy_kernel<<<BATCH, 512>>>();

    // 4) windowed causal attention (shuffle-free)
    attn_kernel<<<512, 128>>>();

    // 5) output projection + bias: 8192 x 512 x 512
    tgemm_h<1><<<dim3(512 / 128, MROWS / 128), 256, HSMEM>>>(zh, wot, bo, out, 512);
}

// round 9
// speedup vs baseline: 2.2236x; 1.0171x over previous
#include <cuda_runtime.h>
#include <cuda_fp16.h>
#include <cstdint>

// ---------------- problem constants ----------------
#define NTOK      4096
#define BATCH     2
#define MROWS     8192
#define NPOS      4095
#define SCALE_Q   0.125f
#define QKVN      1536

// ---------------- scratch ----------------
__device__ __half g_xh   [MROWS * 512];
__device__ float  g_qkv  [MROWS * QKVN];
__device__ __half g_zh   [MROWS * 512];
__device__ __half g_wqkvt[QKVN * 512];
__device__ __half g_wot  [512 * 512];
__device__ float  g_kt   [16 * 64 * NTOK];
__device__ float  g_vt   [16 * 64 * NTOK];

// ---------------- helpers ----------------
__device__ __forceinline__ uint32_t smem_u32(const void* p) {
    uint32_t a;
    asm("{ .reg .u64 t; cvta.to.shared.u64 t, %1; cvt.u32.u64 %0, t; }" : "=r"(a) : "l"(p));
    return a;
}
__device__ __forceinline__ void cp16(uint32_t dst, const void* src) {
    asm volatile("cp.async.cg.shared.global [%0], [%1], 16;" :: "r"(dst), "l"(src));
}
__device__ __forceinline__ void ldsm4(uint32_t& r0, uint32_t& r1, uint32_t& r2, uint32_t& r3, uint32_t a) {
    asm volatile("ldmatrix.sync.aligned.m8n8.x4.shared.b16 {%0,%1,%2,%3}, [%4];"
                 : "=r"(r0), "=r"(r1), "=r"(r2), "=r"(r3) : "r"(a));
}
__device__ __forceinline__ void mma_f16(float& d0, float& d1, float& d2, float& d3,
                                        uint32_t a0, uint32_t a1, uint32_t a2, uint32_t a3,
                                        uint32_t b0, uint32_t b1) {
    asm volatile(
        "mma.sync.aligned.m16n8k16.row.col.f32.f16.f16.f32 "
        "{%0,%1,%2,%3}, {%4,%5,%6,%7}, {%8,%9}, {%0,%1,%2,%3};"
        : "+f"(d0), "+f"(d1), "+f"(d2), "+f"(d3)
        : "r"(a0), "r"(a1), "r"(a2), "r"(a3), "r"(b0), "r"(b1));
}

// ---------------- fused prologue: x->f16 + all three weight transposes ----------------
__device__ __forceinline__ void do_transpose(const float* __restrict__ in, __half* __restrict__ out,
                                             int R, int C, int bx, int by, int tx, int ty,
                                             float (*t)[33])
{
    const int x0 = bx * 32, y0 = by * 32;
    #pragma unroll
    for (int j = 0; j < 32; j += 8)
        t[ty + j][tx] = in[(long)(y0 + ty + j) * C + x0 + tx];
    __syncthreads();
    #pragma unroll
    for (int j = 0; j < 32; j += 8)
        out[(long)(x0 + ty + j) * R + y0 + tx] = __float2half(t[tx][ty + j]);
}

__global__ __launch_bounds__(256)
void prep_kernel(const float* __restrict__ x, const float* __restrict__ Wq,
                 const float* __restrict__ Wkv, const float* __restrict__ Wo)
{
    __shared__ float t[32][33];
    const int blk = blockIdx.x;
    const int tid = threadIdx.x;
    if (blk < 4096) {                              // x -> f16  (4096 * 1024 elements)
        const long i = ((long)blk * 256 + tid) * 4;
        float4 v = *(const float4*)(x + i);
        *(__half2*)(g_xh + i)     = __floats2half2_rn(v.x, v.y);
        *(__half2*)(g_xh + i + 2) = __floats2half2_rn(v.z, v.w);
        return;
    }
    const int tx = tid & 31, ty = tid >> 5;
    if (blk < 4096 + 256) {                        // Wq^T -> wqkvt[0:512]
        const int z = blk - 4096;
        do_transpose(Wq, g_wqkvt, 512, 512, z & 15, z >> 4, tx, ty, t);
    } else if (blk < 4096 + 256 + 512) {           // Wkv^T -> wqkvt[512:1536]
        const int z = blk - 4096 - 256;
        do_transpose(Wkv, g_wqkvt + 512 * 512, 512, 1024, z & 31, z >> 5, tx, ty, t);
    } else {                                       // Wo^T
        const int z = blk - 4096 - 256 - 512;
        do_transpose(Wo, g_wot, 512, 512, z & 15, z >> 4, tx, ty, t);
    }
}

// ---------------- f16 mma GEMM: CTA 128x128, 4 warps (64x64 warp tile), 4-stage ----------------
// A: M x 512 f16 row-major; Bt: N x 512 f16 row-major; C: M x N f32 (+bias)
#define HSTAGE 12288          // A 128x16 @48B stride (6144) + B 128x16 (6144)
#define HSMEM  (4 * HSTAGE)

template<int BIAS>
__global__ __launch_bounds__(128)
void tgemm_h(const __half* __restrict__ A, const __half* __restrict__ Bt,
             const float* __restrict__ bias, float* __restrict__ C, int N)
{
    extern __shared__ char sm[];
    const uint32_t sbase = smem_u32(sm);

    const int tid  = threadIdx.x;
    const int lane = tid & 31;
    const int wid  = tid >> 5;
    const int wm   = wid >> 1;          // 0..1 -> m offset wm*64
    const int wn   = wid & 1;           // 0..1 -> n offset wn*64

    const int row0 = blockIdx.y * 128;
    const int col0 = blockIdx.x * 128;

    const __half* Ap = A  + (long)(row0 + tid) * 512;
    const __half* Bp = Bt + (long)(col0 + tid) * 512;
    const uint32_t dRow = (uint32_t)(tid * 48);

    auto issue_stage = [&](int kk, int s) {
        const uint32_t so = sbase + (uint32_t)s * HSTAGE;
        const long ko = (long)kk * 16;
        cp16(so + dRow,              Ap + ko);
        cp16(so + dRow + 16,         Ap + ko + 8);
        cp16(so + 6144u + dRow,      Bp + ko);
        cp16(so + 6144u + dRow + 16, Bp + ko + 8);
        asm volatile("cp.async.commit_group;" ::: "memory");
    };

    // ldmatrix per-thread offsets
    uint32_t aoff[4], boff[4];
    #pragma unroll
    for (int mt = 0; mt < 4; mt++)
        aoff[mt] = (uint32_t)((wm * 64 + mt * 16 + ((lane >> 3) & 1) * 8 + (lane & 7)) * 48
                              + (lane >> 4) * 16);
    #pragma unroll
    for (int nt = 0; nt < 4; nt++)
        boff[nt] = (uint32_t)((wn * 64 + nt * 16 + ((lane >> 4) & 1) * 8 + (lane & 7)) * 48
                              + ((lane >> 3) & 1) * 16) + 6144u;

    float acc[4][8][4];
    #pragma unroll
    for (int mt = 0; mt < 4; mt++)
        #pragma unroll
        for (int nb = 0; nb < 8; nb++)
            #pragma unroll
            for (int e = 0; e < 4; e++) acc[mt][nb][e] = 0.f;

    issue_stage(0, 0);
    issue_stage(1, 1);
    issue_stage(2, 2);

    for (int kk = 0; kk < 32; kk++) {
        asm volatile("cp.async.wait_group 2;" ::: "memory");
        __syncthreads();

        if (kk + 3 < 32) issue_stage(kk + 3, (kk + 3) & 3);
        else asm volatile("cp.async.commit_group;" ::: "memory");

        const uint32_t sa = sbase + (uint32_t)(kk & 3) * HSTAGE;

        uint32_t af[4][4], bfr[4][4];
        #pragma unroll
        for (int mt = 0; mt < 4; mt++)
            ldsm4(af[mt][0], af[mt][1], af[mt][2], af[mt][3], sa + aoff[mt]);
        #pragma unroll
        for (int nt = 0; nt < 4; nt++)
            ldsm4(bfr[nt][0], bfr[nt][1], bfr[nt][2], bfr[nt][3], sa + boff[nt]);

        #pragma unroll
        for (int mt = 0; mt < 4; mt++)
            #pragma unroll
            for (int nt = 0; nt < 4; nt++) {
                mma_f16(acc[mt][2*nt][0], acc[mt][2*nt][1], acc[mt][2*nt][2], acc[mt][2*nt][3],
                        af[mt][0], af[mt][1], af[mt][2], af[mt][3],
                        bfr[nt][0], bfr[nt][1]);
                mma_f16(acc[mt][2*nt+1][0], acc[mt][2*nt+1][1], acc[mt][2*nt+1][2], acc[mt][2*nt+1][3],
                        af[mt][0], af[mt][1], af[mt][2], af[mt][3],
                        bfr[nt][2], bfr[nt][3]);
            }
    }

    // epilogue
    const int r  = lane >> 2;
    const int cp = (lane & 3) * 2;
    #pragma unroll
    for (int mt = 0; mt < 4; mt++) {
        #pragma unroll
        for (int nb = 0; nb < 8; nb++) {
            const int cc = col0 + wn * 64 + nb * 8 + cp;
            float bx = 0.f, by = 0.f;
            if (BIAS) { bx = bias[cc]; by = bias[cc + 1]; }
            const long r1 = row0 + wm * 64 + mt * 16 + r;
            *(float2*)(C + r1 * N + cc)       = make_float2(acc[mt][nb][0] + bx, acc[mt][nb][1] + by);
            *(float2*)(C + (r1 + 8) * N + cc) = make_float2(acc[mt][nb][2] + bx, acc[mt][nb][3] + by);
        }
    }
}

// ---------------- fused k/v transpose + BOS rows ----------------
__global__ __launch_bounds__(256)
void kvt_bos_kernel()
{
    __shared__ float tl[32][33];
    const int blk = blockIdx.x;
    const int tid = threadIdx.x;

    if (blk == 8192) {         // BOS: zh[b,0,:] = f16(v(token 0))
        #pragma unroll
        for (int e = tid; e < 1024; e += 256) {
            const int b = e >> 9, t = e & 511;
            g_zh[(long)b * NTOK * 512 + t] = __float2half(g_qkv[(long)b * NTOK * QKVN + 1024 + t]);
        }
        return;
    }

    const int tx = tid & 31, ty = tid >> 5;
    const int t0 = (blk & 127) * 32;
    const int dh = (blk >> 7) & 1;
    const int z  = blk >> 8;
    const int which = z & 1;
    const int bh = z >> 1;
    const int b  = bh >> 3;
    const int h  = bh & 7;

    const float* src = g_qkv + 512 + which * 512 + h * 64 + dh * 32;
    #pragma unroll
    for (int j = 0; j < 32; j += 8)
        tl[ty + j][tx] = src[(long)(b * NTOK + t0 + ty + j) * QKVN + tx];
    __syncthreads();
    float* dst = (which ? g_vt : g_kt) + (long)(bh * 64 + dh * 32) * NTOK;
    #pragma unroll
    for (int j = 0; j < 32; j += 8)
        dst[(long)(ty + j) * NTOK + t0 + tx] = tl[tx][ty + j];
}

// ---------------- windowed attention: lane = query, no shuffles ----------------
__constant__ int C_DF[14] = {-1,-1,-1,-1,-1,-1,-1,-1,-1, 0, 0, 0, 0, 0};
__constant__ int C_DH[14] = {-1,-1,-1, 0, 0, 0, 1, 1, 1,-1,-1,-1, 0, 0};
__constant__ int C_DW[14] = {-1, 0, 1,-1, 0, 1,-1, 0, 1,-1, 0, 1,-1, 0};

__global__ __launch_bounds__(128, 4)
void attn_kernel()
{
    __shared__ float ssm[4][2112];

    const int w    = threadIdx.x >> 5;
    const int lane = threadIdx.x & 31;
    const int widx = blockIdx.x * 4 + w;
    const int grp  = widx & 127;
    const int bh   = widx >> 7;
    const int b    = bh >> 3;
    const int h    = bh & 7;
    const int i0   = grp * 32;
    const int f    = i0 >> 10;
    const int hh   = (i0 >> 5) & 31;
    const int i    = i0 + lane;

    float* qs = ssm[w];

    for (int r = 0; r < 32; r++) {
        const int tk = min(i0 + r, NPOS - 1) + 1;
        float2 v = *(const float2*)(g_qkv + (long)(b * NTOK + tk) * QKVN + h * 64 + 2 * lane);
        qs[r * 65 + 2 * lane]     = v.x;
        qs[r * 65 + 2 * lane + 1] = v.y;
    }
    __syncwarp();
    float q[64];
    #pragma unroll
    for (int d = 0; d < 64; d++) q[d] = qs[lane * 65 + d] * SCALE_Q;
    __syncwarp();

    const float NEG_INF = __int_as_float(0xff800000);
    const float* ktb = g_kt + (long)bh * 64 * NTOK;
    const float* vtb = g_vt + (long)bh * 64 * NTOK;

    float sim[15];
    int   tok[15];
    int   wok[15];

    {
        tok[0] = 0; wok[0] = 1;
        float s0 = 0.f, s1 = 0.f, s2 = 0.f, s3 = 0.f;
        #pragma unroll
        for (int d = 0; d < 64; d += 4) {
            s0 += q[d]     * ktb[(long)d * NTOK];
            s1 += q[d + 1] * ktb[(long)(d + 1) * NTOK];
            s2 += q[d + 2] * ktb[(long)(d + 2) * NTOK];
            s3 += q[d + 3] * ktb[(long)(d + 3) * NTOK];
        }
        sim[0] = (s0 + s1) + (s2 + s3);
    }

    #pragma unroll
    for (int s = 0; s < 14; s++) {
        const int df = C_DF[s], dh = C_DH[s], dw = C_DW[s];
        const int off = df * 1024 + dh * 32 + dw;
        const int warp_ok = (f + df >= 0) && ((unsigned)(hh + dh) < 32u);
        wok[s + 1] = warp_ok;
        sim[s + 1] = NEG_INF;
        int t = 0;
        if (warp_ok) {
            const int lane_ok = ((unsigned)(lane + dw) < 32u) && (i < NPOS);
            t = min(max(i + off, 0), NPOS - 1) + 1;
            float s0 = 0.f, s1 = 0.f, s2 = 0.f, s3 = 0.f;
            const float* kp = ktb + t;
            #pragma unroll
            for (int d = 0; d < 64; d += 4) {
                s0 += q[d]     * kp[(long)d * NTOK];
                s1 += q[d + 1] * kp[(long)(d + 1) * NTOK];
                s2 += q[d + 2] * kp[(long)(d + 2) * NTOK];
                s3 += q[d + 3] * kp[(long)(d + 3) * NTOK];
            }
            if (lane_ok) sim[s + 1] = (s0 + s1) + (s2 + s3);
        }
        tok[s + 1] = t;
    }

    float m = sim[0];
    #pragma unroll
    for (int s = 1; s < 15; s++) m = fmaxf(m, sim[s]);
    float p[15], den = 0.f;
    #pragma unroll
    for (int s = 0; s < 15; s++) { p[s] = __expf(sim[s] - m); den += p[s]; }
    const float inv = 1.f / den;
    #pragma unroll
    for (int s = 0; s < 15; s++) p[s] *= inv;

    float* osm = ssm[w];
    for (int d = 0; d < 64; d += 2) {
        const float* vp0 = vtb + (long)d * NTOK;
        const float* vp1 = vtb + (long)(d + 1) * NTOK;
        float a0 = 0.f, a1 = 0.f;
        #pragma unroll
        for (int s = 0; s < 15; s++) {
            if (wok[s]) {
                a0 += p[s] * vp0[tok[s]];
                a1 += p[s] * vp1[tok[s]];
            }
        }
        osm[d * 33 + lane]       = a0;
        osm[(d + 1) * 33 + lane] = a1;
    }
    __syncwarp();

    for (int rr = 0; rr < 32; rr++) {
        const int irow = i0 + rr;
        if (irow < NPOS) {
            const float x0 = osm[(2 * lane) * 33 + rr];
            const float x1 = osm[(2 * lane + 1) * 33 + rr];
            *(__half2*)(g_zh + (long)(b * NTOK + irow + 1) * 512 + h * 64 + 2 * lane)
                = __floats2half2_rn(x0, x1);
        }
    }
}

// ---------------- launch ----------------
extern "C" void kernel_launch(void* const* d_in, const int* in_sizes, int n_in,
                              void* d_out, int out_size)
{
    const float* x   = (const float*)d_in[0];
    const float* Wq  = (const float*)d_in[1];
    const float* Wkv = (const float*)d_in[2];
    const float* Wo  = (const float*)d_in[3];
    const float* bo  = (const float*)d_in[4];
    float* out = (float*)d_out;

    __half *xh, *wqkvt, *wot, *zh;
    float *qkv;
    cudaGetSymbolAddress((void**)&xh,    g_xh);
    cudaGetSymbolAddress((void**)&qkv,   g_qkv);
    cudaGetSymbolAddress((void**)&zh,    g_zh);
    cudaGetSymbolAddress((void**)&wqkvt, g_wqkvt);
    cudaGetSymbolAddress((void**)&wot,   g_wot);

    cudaFuncSetAttribute(tgemm_h<0>, cudaFuncAttributeMaxDynamicSharedMemorySize, HSMEM);
    cudaFuncSetAttribute(tgemm_h<1>, cudaFuncAttributeMaxDynamicSharedMemorySize, HSMEM);

    // 0) fused prologue
    prep_kernel<<<4096 + 256 + 512 + 256, 256>>>(x, Wq, Wkv, Wo);

    // 1) fused QKV projection: 8192 x 1536 x 512
    tgemm_h<0><<<dim3(QKVN / 128, MROWS / 128), 128, HSMEM>>>(xh, wqkvt, nullptr, qkv, QKVN);

    // 2) k/v transpose + BOS rows
    kvt_bos_kernel<<<8193, 256>>>();

    // 3) windowed causal attention
    attn_kernel<<<512, 128>>>();

    // 4) output projection + bias
    tgemm_h<1><<<dim3(512 / 128, MROWS / 128), 128, HSMEM>>>(zh, wot, bo, out, 512);
}

// round 10
// speedup vs baseline: 3.4677x; 1.5595x over previous
#include <cuda_runtime.h>
#include <cuda_fp16.h>
#include <cstdint>

// ---------------- problem constants ----------------
#define NTOK      4096
#define BATCH     2
#define MROWS     8192
#define NPOS      4095
#define SCALE_Q   0.125f
#define QKVN      1536

// ---------------- scratch ----------------
__device__ __half g_xh   [MROWS * 512];
__device__ float  g_qkv  [MROWS * QKVN];
__device__ __half g_zh   [MROWS * 512];
__device__ __half g_wqkvt[QKVN * 512];
__device__ __half g_wot  [512 * 512];
__device__ float  g_kt   [16 * 64 * NTOK];
__device__ float  g_vt   [16 * 64 * NTOK];

// ---------------- helpers ----------------
__device__ __forceinline__ uint32_t smem_u32(const void* p) {
    uint32_t a;
    asm("{ .reg .u64 t; cvta.to.shared.u64 t, %1; cvt.u32.u64 %0, t; }" : "=r"(a) : "l"(p));
    return a;
}
__device__ __forceinline__ void cp16(uint32_t dst, const void* src) {
    asm volatile("cp.async.cg.shared.global [%0], [%1], 16;" :: "r"(dst), "l"(src));
}
__device__ __forceinline__ void ldsm4(uint32_t& r0, uint32_t& r1, uint32_t& r2, uint32_t& r3, uint32_t a) {
    asm volatile("ldmatrix.sync.aligned.m8n8.x4.shared.b16 {%0,%1,%2,%3}, [%4];"
                 : "=r"(r0), "=r"(r1), "=r"(r2), "=r"(r3) : "r"(a));
}
__device__ __forceinline__ void mma_f16(float& d0, float& d1, float& d2, float& d3,
                                        uint32_t a0, uint32_t a1, uint32_t a2, uint32_t a3,
                                        uint32_t b0, uint32_t b1) {
    asm volatile(
        "mma.sync.aligned.m16n8k16.row.col.f32.f16.f16.f32 "
        "{%0,%1,%2,%3}, {%4,%5,%6,%7}, {%8,%9}, {%0,%1,%2,%3};"
        : "+f"(d0), "+f"(d1), "+f"(d2), "+f"(d3)
        : "r"(a0), "r"(a1), "r"(a2), "r"(a3), "r"(b0), "r"(b1));
}

// ---------------- fused prologue: x->f16 + all three weight transposes ----------------
__device__ __forceinline__ void do_transpose(const float* __restrict__ in, __half* __restrict__ out,
                                             int R, int C, int bx, int by, int tx, int ty,
                                             float (*t)[33])
{
    const int x0 = bx * 32, y0 = by * 32;
    #pragma unroll
    for (int j = 0; j < 32; j += 8)
        t[ty + j][tx] = in[(long)(y0 + ty + j) * C + x0 + tx];
    __syncthreads();
    #pragma unroll
    for (int j = 0; j < 32; j += 8)
        out[(long)(x0 + ty + j) * R + y0 + tx] = __float2half(t[tx][ty + j]);
}

__global__ __launch_bounds__(256)
void prep_kernel(const float* __restrict__ x, const float* __restrict__ Wq,
                 const float* __restrict__ Wkv, const float* __restrict__ Wo)
{
    __shared__ float t[32][33];
    const int blk = blockIdx.x;
    const int tid = threadIdx.x;
    if (blk < 4096) {
        const long i = ((long)blk * 256 + tid) * 4;
        float4 v = *(const float4*)(x + i);
        *(__half2*)(g_xh + i)     = __floats2half2_rn(v.x, v.y);
        *(__half2*)(g_xh + i + 2) = __floats2half2_rn(v.z, v.w);
        return;
    }
    const int tx = tid & 31, ty = tid >> 5;
    if (blk < 4096 + 256) {
        const int z = blk - 4096;
        do_transpose(Wq, g_wqkvt, 512, 512, z & 15, z >> 4, tx, ty, t);
    } else if (blk < 4096 + 256 + 512) {
        const int z = blk - 4096 - 256;
        do_transpose(Wkv, g_wqkvt + 512 * 512, 512, 1024, z & 31, z >> 5, tx, ty, t);
    } else {
        const int z = blk - 4096 - 256 - 512;
        do_transpose(Wo, g_wot, 512, 512, z & 15, z >> 4, tx, ty, t);
    }
}

// ---------------- f16 mma GEMM: CTA 128x128, 4 warps (64x64 warp tile), 4-stage ----------------
#define HSTAGE 12288
#define HSMEM  (4 * HSTAGE)

template<int BIAS>
__global__ __launch_bounds__(128)
void tgemm_h(const __half* __restrict__ A, const __half* __restrict__ Bt,
             const float* __restrict__ bias, float* __restrict__ C, int N)
{
    extern __shared__ char sm[];
    const uint32_t sbase = smem_u32(sm);

    const int tid  = threadIdx.x;
    const int lane = tid & 31;
    const int wid  = tid >> 5;
    const int wm   = wid >> 1;
    const int wn   = wid & 1;

    const int row0 = blockIdx.y * 128;
    const int col0 = blockIdx.x * 128;

    const __half* Ap = A  + (long)(row0 + tid) * 512;
    const __half* Bp = Bt + (long)(col0 + tid) * 512;
    const uint32_t dRow = (uint32_t)(tid * 48);

    auto issue_stage = [&](int kk, int s) {
        const uint32_t so = sbase + (uint32_t)s * HSTAGE;
        const long ko = (long)kk * 16;
        cp16(so + dRow,              Ap + ko);
        cp16(so + dRow + 16,         Ap + ko + 8);
        cp16(so + 6144u + dRow,      Bp + ko);
        cp16(so + 6144u + dRow + 16, Bp + ko + 8);
        asm volatile("cp.async.commit_group;" ::: "memory");
    };

    uint32_t aoff[4], boff[4];
    #pragma unroll
    for (int mt = 0; mt < 4; mt++)
        aoff[mt] = (uint32_t)((wm * 64 + mt * 16 + ((lane >> 3) & 1) * 8 + (lane & 7)) * 48
                              + (lane >> 4) * 16);
    #pragma unroll
    for (int nt = 0; nt < 4; nt++)
        boff[nt] = (uint32_t)((wn * 64 + nt * 16 + ((lane >> 4) & 1) * 8 + (lane & 7)) * 48
                              + ((lane >> 3) & 1) * 16) + 6144u;

    float acc[4][8][4];
    #pragma unroll
    for (int mt = 0; mt < 4; mt++)
        #pragma unroll
        for (int nb = 0; nb < 8; nb++)
            #pragma unroll
            for (int e = 0; e < 4; e++) acc[mt][nb][e] = 0.f;

    issue_stage(0, 0);
    issue_stage(1, 1);
    issue_stage(2, 2);

    for (int kk = 0; kk < 32; kk++) {
        asm volatile("cp.async.wait_group 2;" ::: "memory");
        __syncthreads();

        if (kk + 3 < 32) issue_stage(kk + 3, (kk + 3) & 3);
        else asm volatile("cp.async.commit_group;" ::: "memory");

        const uint32_t sa = sbase + (uint32_t)(kk & 3) * HSTAGE;

        uint32_t af[4][4], bfr[4][4];
        #pragma unroll
        for (int mt = 0; mt < 4; mt++)
            ldsm4(af[mt][0], af[mt][1], af[mt][2], af[mt][3], sa + aoff[mt]);
        #pragma unroll
        for (int nt = 0; nt < 4; nt++)
            ldsm4(bfr[nt][0], bfr[nt][1], bfr[nt][2], bfr[nt][3], sa + boff[nt]);

        #pragma unroll
        for (int mt = 0; mt < 4; mt++)
            #pragma unroll
            for (int nt = 0; nt < 4; nt++) {
                mma_f16(acc[mt][2*nt][0], acc[mt][2*nt][1], acc[mt][2*nt][2], acc[mt][2*nt][3],
                        af[mt][0], af[mt][1], af[mt][2], af[mt][3],
                        bfr[nt][0], bfr[nt][1]);
                mma_f16(acc[mt][2*nt+1][0], acc[mt][2*nt+1][1], acc[mt][2*nt+1][2], acc[mt][2*nt+1][3],
                        af[mt][0], af[mt][1], af[mt][2], af[mt][3],
                        bfr[nt][2], bfr[nt][3]);
            }
    }

    const int r  = lane >> 2;
    const int cp = (lane & 3) * 2;
    #pragma unroll
    for (int mt = 0; mt < 4; mt++) {
        #pragma unroll
        for (int nb = 0; nb < 8; nb++) {
            const int cc = col0 + wn * 64 + nb * 8 + cp;
            float bx = 0.f, by = 0.f;
            if (BIAS) { bx = bias[cc]; by = bias[cc + 1]; }
            const long r1 = row0 + wm * 64 + mt * 16 + r;
            *(float2*)(C + r1 * N + cc)       = make_float2(acc[mt][nb][0] + bx, acc[mt][nb][1] + by);
            *(float2*)(C + (r1 + 8) * N + cc) = make_float2(acc[mt][nb][2] + bx, acc[mt][nb][3] + by);
        }
    }
}

// ---------------- fused k/v transpose + BOS rows ----------------
__global__ __launch_bounds__(256)
void kvt_bos_kernel()
{
    __shared__ float tl[32][33];
    const int blk = blockIdx.x;
    const int tid = threadIdx.x;

    if (blk == 8192) {
        #pragma unroll
        for (int e = tid; e < 1024; e += 256) {
            const int b = e >> 9, t = e & 511;
            g_zh[(long)b * NTOK * 512 + t] = __float2half(g_qkv[(long)b * NTOK * QKVN + 1024 + t]);
        }
        return;
    }

    const int tx = tid & 31, ty = tid >> 5;
    const int t0 = (blk & 127) * 32;
    const int dh = (blk >> 7) & 1;
    const int z  = blk >> 8;
    const int which = z & 1;
    const int bh = z >> 1;
    const int b  = bh >> 3;
    const int h  = bh & 7;

    const float* src = g_qkv + 512 + which * 512 + h * 64 + dh * 32;
    #pragma unroll
    for (int j = 0; j < 32; j += 8)
        tl[ty + j][tx] = src[(long)(b * NTOK + t0 + ty + j) * QKVN + tx];
    __syncthreads();
    float* dst = (which ? g_vt : g_kt) + (long)(bh * 64 + dh * 32) * NTOK;
    #pragma unroll
    for (int j = 0; j < 32; j += 8)
        dst[(long)(ty + j) * NTOK + t0 + tx] = tl[tx][ty + j];
}

// ---------------- windowed attention: d-split across 4 warps ----------------
// block = (bh, 32-query tile), 128 threads; warp w owns d [16w, 16w+16)
__constant__ int C_DF[14] = {-1,-1,-1,-1,-1,-1,-1,-1,-1, 0, 0, 0, 0, 0};
__constant__ int C_DH[14] = {-1,-1,-1, 0, 0, 0, 1, 1, 1,-1,-1,-1, 0, 0};
__constant__ int C_DW[14] = {-1, 0, 1,-1, 0, 1,-1, 0, 1,-1, 0, 1,-1, 0};

__global__ __launch_bounds__(128, 6)
void attn_kernel()
{
    __shared__ float qs[2112];           // q staging (stride 65), then output (stride 33)
    __shared__ float ps[4][15][32];      // per-warp partial sims

    const int tid  = threadIdx.x;
    const int w    = tid >> 5;
    const int lane = tid & 31;
    const int blk  = blockIdx.x;         // 0..2047
    const int grp  = blk & 127;
    const int bh   = blk >> 7;
    const int b    = bh >> 3;
    const int h    = bh & 7;
    const int i0   = grp * 32;
    const int f    = i0 >> 10;
    const int hh   = (i0 >> 5) & 31;
    const int i    = i0 + lane;

    // ---- stage q (coalesced): thread -> (row tid>>2, 16 cols) ----
    {
        const int r = tid >> 2;
        const int c = (tid & 3) * 16;
        const int tk = min(i0 + r, NPOS - 1) + 1;
        const float* src = g_qkv + (long)(b * NTOK + tk) * QKVN + h * 64 + c;
        #pragma unroll
        for (int j = 0; j < 16; j += 4) {
            float4 v = *(const float4*)(src + j);
            qs[r * 65 + c + j]     = v.x;
            qs[r * 65 + c + j + 1] = v.y;
            qs[r * 65 + c + j + 2] = v.z;
            qs[r * 65 + c + j + 3] = v.w;
        }
    }
    __syncthreads();

    // per-lane q chunk (16 regs)
    float q[16];
    #pragma unroll
    for (int j = 0; j < 16; j++) q[j] = qs[lane * 65 + w * 16 + j] * SCALE_Q;

    const float* ktb = g_kt + ((long)bh * 64 + w * 16) * NTOK;
    const float* vtb = g_vt + ((long)bh * 64 + w * 16) * NTOK;

    int tok[15];

    // ---- partial sims ----
    {   // BOS
        tok[0] = 0;
        float a0 = 0.f, a1 = 0.f;
        #pragma unroll
        for (int d = 0; d < 16; d += 2) {
            a0 += q[d]     * ktb[(long)d * NTOK];
            a1 += q[d + 1] * ktb[(long)(d + 1) * NTOK];
        }
        ps[w][0][lane] = a0 + a1;
    }
    #pragma unroll
    for (int s = 0; s < 14; s++) {
        const int df = C_DF[s], dh = C_DH[s], dw = C_DW[s];
        const int off = df * 1024 + dh * 32 + dw;
        const int warp_ok = (f + df >= 0) && ((unsigned)(hh + dh) < 32u);
        int t = 0;
        float acc = 0.f;
        if (warp_ok) {
            t = min(max(i + off, 0), NPOS - 1) + 1;
            const float* kp = ktb + t;
            float a0 = 0.f, a1 = 0.f;
            #pragma unroll
            for (int d = 0; d < 16; d += 2) {
                a0 += q[d]     * kp[(long)d * NTOK];
                a1 += q[d + 1] * kp[(long)(d + 1) * NTOK];
            }
            acc = a0 + a1;
        }
        tok[s + 1] = t;
        ps[w][s + 1][lane] = acc;
    }
    __syncthreads();

    // ---- combine + softmax (each warp redundantly) ----
    const float NEG_INF = __int_as_float(0xff800000);
    float p[15];
    {
        p[0] = ps[0][0][lane] + ps[1][0][lane] + ps[2][0][lane] + ps[3][0][lane];
        #pragma unroll
        for (int s = 0; s < 14; s++) {
            const int df = C_DF[s], dh = C_DH[s], dw = C_DW[s];
            const int ok = (f + df >= 0) && ((unsigned)(hh + dh) < 32u)
                        && ((unsigned)(lane + dw) < 32u) && (i < NPOS);
            p[s + 1] = ok ? (ps[0][s + 1][lane] + ps[1][s + 1][lane]
                           + ps[2][s + 1][lane] + ps[3][s + 1][lane]) : NEG_INF;
        }
        float m = p[0];
        #pragma unroll
        for (int s = 1; s < 15; s++) m = fmaxf(m, p[s]);
        float den = 0.f;
        #pragma unroll
        for (int s = 0; s < 15; s++) { p[s] = __expf(p[s] - m); den += p[s]; }
        const float inv = 1.f / den;
        #pragma unroll
        for (int s = 0; s < 15; s++) p[s] *= inv;
    }

    // ---- PV: warp computes its 16-d slice ----
    float o[16];
    #pragma unroll
    for (int d = 0; d < 16; d++) o[d] = 0.f;
    {   // BOS
        const float pw = p[0];
        #pragma unroll
        for (int d = 0; d < 16; d++) o[d] += pw * vtb[(long)d * NTOK];
    }
    #pragma unroll
    for (int s = 0; s < 14; s++) {
        const int df = C_DF[s], dh = C_DH[s];
        const int warp_ok = (f + df >= 0) && ((unsigned)(hh + dh) < 32u);
        if (warp_ok) {
            const float pw = p[s + 1];
            const float* vp = vtb + tok[s + 1];
            #pragma unroll
            for (int d = 0; d < 16; d++) o[d] += pw * vp[(long)d * NTOK];
        }
    }
    __syncthreads();   // qs reads all done -> reuse as output staging

    #pragma unroll
    for (int d = 0; d < 16; d++) qs[(w * 16 + d) * 33 + lane] = o[d];
    __syncthreads();

    // ---- coalesced f16 store: thread -> (row tid>>2, 16 cols) ----
    {
        const int r = tid >> 2;
        const int c = (tid & 3) * 16;
        const int irow = i0 + r;
        if (irow < NPOS) {
            __half* dst = g_zh + (long)(b * NTOK + irow + 1) * 512 + h * 64 + c;
            #pragma unroll
            for (int j = 0; j < 16; j += 2) {
                const float x0 = qs[(c + j) * 33 + r];
                const float x1 = qs[(c + j + 1) * 33 + r];
                *(__half2*)(dst + j) = __floats2half2_rn(x0, x1);
            }
        }
    }
}

// ---------------- launch ----------------
extern "C" void kernel_launch(void* const* d_in, const int* in_sizes, int n_in,
                              void* d_out, int out_size)
{
    const float* x   = (const float*)d_in[0];
    const float* Wq  = (const float*)d_in[1];
    const float* Wkv = (const float*)d_in[2];
    const float* Wo  = (const float*)d_in[3];
    const float* bo  = (const float*)d_in[4];
    float* out = (float*)d_out;

    __half *xh, *wqkvt, *wot, *zh;
    float *qkv;
    cudaGetSymbolAddress((void**)&xh,    g_xh);
    cudaGetSymbolAddress((void**)&qkv,   g_qkv);
    cudaGetSymbolAddress((void**)&zh,    g_zh);
    cudaGetSymbolAddress((void**)&wqkvt, g_wqkvt);
    cudaGetSymbolAddress((void**)&wot,   g_wot);

    cudaFuncSetAttribute(tgemm_h<0>, cudaFuncAttributeMaxDynamicSharedMemorySize, HSMEM);
    cudaFuncSetAttribute(tgemm_h<1>, cudaFuncAttributeMaxDynamicSharedMemorySize, HSMEM);

    // 0) fused prologue
    prep_kernel<<<4096 + 256 + 512 + 256, 256>>>(x, Wq, Wkv, Wo);

    // 1) fused QKV projection: 8192 x 1536 x 512
    tgemm_h<0><<<dim3(QKVN / 128, MROWS / 128), 128, HSMEM>>>(xh, wqkvt, nullptr, qkv, QKVN);

    // 2) k/v transpose + BOS rows
    kvt_bos_kernel<<<8193, 256>>>();

    // 3) windowed causal attention (d-split, 8192 warps)
    attn_kernel<<<2048, 128>>>();

    // 4) output projection + bias
    tgemm_h<1><<<dim3(512 / 128, MROWS / 128), 128, HSMEM>>>(zh, wot, bo, out, 512);
}